// round 4
// baseline (speedup 1.0000x reference)
#include <cuda_runtime.h>

// LIF neuron with cache term (derivation in earlier rounds):
//   mem   = mem/TAU + (1 + ALPHA*cache) * x_t
//   spike = (mem - V_TH > 0); mem = (1-spike)*mem; cache = BETA*cache + (1-spike)
//
// X: [B=32, T=64, N=32768] f32 -> spikes, same shape. Pure streaming.
//
// Bottleneck analysis (R3): DRAM 75% active with issue 34% = MLP
// shortfall (~10KB in flight per SM vs ~15.5KB needed), caused by
// regs=32 limiting register-backed load buffers to ~1.5 per warp.
// Fix: prefetch.global.L2 at distance 4 — adds request depth with
// zero register cost; demand loads then hit L2 (~234cyc vs ~577cyc),
// which the existing buffering covers.
//
// Division by TAU=5 via residual-corrected FMA triple — provably
// bit-identical to __fdiv_rn(x,5) for all floats. All other ops use
// explicit __f*_rn (no FMA contraction) to bit-match the XLA
// reference; threshold flips would cascade across the T recurrence.

constexpr int B = 32;
constexpr int T = 64;
constexpr int N = 32768;
constexpr int N4 = N / 4;           // 8192 float4 per (b, t) row

__device__ __forceinline__ float div5_exact(float x) {
    const float y = 0.2f;                       // RN(1/5)
    float q = __fmul_rn(x, y);
    float r = __fmaf_rn(q, -5.0f, x);           // exact residual
    return __fmaf_rn(r, y, q);                  // == __fdiv_rn(x, 5.0f)
}

__device__ __forceinline__ float lif_step(float x, float& mem, float& cache) {
    float d = div5_exact(mem);                              // mem / TAU
    float g = __fadd_rn(1.0f, __fmul_rn(0.1f, cache));      // 1 + ALPHA*cache
    mem = __fadd_rn(d, __fmul_rn(g, x));
    bool fired = (mem > 0.5f);                              // mem - V_TH > 0
    float spike = fired ? 1.0f : 0.0f;
    mem = fired ? 0.0f : mem;                               // hard reset to 0
    cache = __fadd_rn(__fmul_rn(0.5f, cache), fired ? 0.0f : 1.0f);
    return spike;
}

__device__ __forceinline__ void prefetch_l2(const void* p) {
    asm volatile("prefetch.global.L2 [%0];" :: "l"(p));
}

__global__ __launch_bounds__(256) void lif_kernel(
    const float4* __restrict__ X, float4* __restrict__ out)
{
    int lane = blockIdx.x * blockDim.x + threadIdx.x;   // [0, B*N4)
    int b = lane >> 13;                                  // lane / N4
    int c = lane & (N4 - 1);                             // lane % N4
    int base = b * (T * N4) + c;

    float4 mem   = make_float4(0.f, 0.f, 0.f, 0.f);
    float4 cache = make_float4(0.f, 0.f, 0.f, 0.f);

    // Warm the L2 pipeline: steps 1..3 prefetched, step 0 demand-loaded.
    prefetch_l2(&X[base + 1 * N4]);
    prefetch_l2(&X[base + 2 * N4]);
    prefetch_l2(&X[base + 3 * N4]);
    float4 x = __ldcs(&X[base]);

#pragma unroll 8
    for (int t = 0; t < T; ++t) {
        int tp = min(t + 4, T - 1);
        prefetch_l2(&X[base + tp * N4]);          // depth-4 request stream

        int tn = min(t + 1, T - 1);
        float4 xn = __ldcs(&X[base + tn * N4]);   // should hit L2

        float4 s;
        s.x = lif_step(x.x, mem.x, cache.x);
        s.y = lif_step(x.y, mem.y, cache.y);
        s.z = lif_step(x.z, mem.z, cache.z);
        s.w = lif_step(x.w, mem.w, cache.w);

        __stcs(&out[base + t * N4], s);
        x = xn;
    }
}

extern "C" void kernel_launch(void* const* d_in, const int* in_sizes, int n_in,
                              void* d_out, int out_size) {
    const float4* X = (const float4*)d_in[0];
    float4* out = (float4*)d_out;
    int lanes = B * N4;                 // 262,144
    lif_kernel<<<lanes / 256, 256>>>(X, out);
}

// round 6
// speedup vs baseline: 1.0239x; 1.0239x over previous
#include <cuda_runtime.h>

// LIF neuron with cache term:
//   mem   = mem/TAU + (1 + ALPHA*cache) * x_t
//   spike = (mem - V_TH > 0); mem = (1-spike)*mem; cache = BETA*cache + (1-spike)
//
// X: [B=32, T=64, N=32768] f32 -> spikes, same shape. Pure streaming.
//
// R4 post-mortem: DRAM pinned ~75% because regs=32 holds only ~1
// outstanding float4 load per warp (~6.6KB/SM in flight vs ~8.5KB
// needed at NAT latency). Fix: per-thread cp.async.cg (LDGSTS) into a
// 4-stage SMEM ring — outstanding bytes become ~48B/thread (~80KB/SM)
// with zero register cost and no __syncthreads (each thread reads only
// the bytes it copied; cp.async.wait_group gives per-thread ordering).
//
// Division by TAU=5 via residual-corrected FMA triple — provably
// bit-identical to __fdiv_rn(x,5) for all floats. All other ops use
// explicit __f*_rn (no FMA contraction) to bit-match the XLA
// reference; a single threshold flip would cascade across T.

constexpr int B = 32;
constexpr int T = 64;
constexpr int N = 32768;
constexpr int N4 = N / 4;           // 8192 float4 per (b, t) row
constexpr int THREADS = 256;
constexpr int STAGES = 4;           // smem ring depth (16KB/CTA)

__device__ __forceinline__ float div5_exact(float x) {
    const float y = 0.2f;                       // RN(1/5)
    float q = __fmul_rn(x, y);
    float r = __fmaf_rn(q, -5.0f, x);           // exact residual
    return __fmaf_rn(r, y, q);                  // == __fdiv_rn(x, 5.0f)
}

__device__ __forceinline__ float lif_step(float x, float& mem, float& cache) {
    float d = div5_exact(mem);                              // mem / TAU
    float g = __fadd_rn(1.0f, __fmul_rn(0.1f, cache));      // 1 + ALPHA*cache
    mem = __fadd_rn(d, __fmul_rn(g, x));
    bool fired = (mem > 0.5f);                              // mem - V_TH > 0
    float spike = fired ? 1.0f : 0.0f;
    mem = fired ? 0.0f : mem;                               // hard reset to 0
    cache = __fadd_rn(__fmul_rn(0.5f, cache), fired ? 0.0f : 1.0f);
    return spike;
}

__device__ __forceinline__ void cp_async16(float4* smem, const float4* gmem) {
    unsigned int s = (unsigned int)__cvta_generic_to_shared(smem);
    asm volatile("cp.async.cg.shared.global [%0], [%1], 16;"
                 :: "r"(s), "l"(gmem) : "memory");
}
__device__ __forceinline__ void cp_commit() {
    asm volatile("cp.async.commit_group;" ::: "memory");
}
template <int Nwait>
__device__ __forceinline__ void cp_wait() {
    asm volatile("cp.async.wait_group %0;" :: "n"(Nwait) : "memory");
}

__global__ __launch_bounds__(THREADS) void lif_kernel(
    const float4* __restrict__ X, float4* __restrict__ out)
{
    __shared__ float4 buf[STAGES][THREADS];

    int tid  = threadIdx.x;
    int lane = blockIdx.x * THREADS + tid;              // [0, B*N4)
    int b = lane >> 13;                                  // lane / N4
    int c = lane & (N4 - 1);                             // lane % N4
    int base = b * (T * N4) + c;

    // Prologue: fill the ring, one commit group per stage.
#pragma unroll
    for (int s = 0; s < STAGES; ++s) {
        cp_async16(&buf[s][tid], &X[base + s * N4]);
        cp_commit();
    }

    float4 mem   = make_float4(0.f, 0.f, 0.f, 0.f);
    float4 cache = make_float4(0.f, 0.f, 0.f, 0.f);

#pragma unroll 4
    for (int t = 0; t < T; ++t) {
        cp_wait<STAGES - 1>();                // stage-t copy complete
        int slot = t & (STAGES - 1);
        float4 x = buf[slot][tid];            // LDS: only own bytes

        // Refill this slot for step t+STAGES (predicated; empty
        // commit_group at the tail is legal and completes instantly).
        if (t + STAGES < T)
            cp_async16(&buf[slot][tid], &X[base + (t + STAGES) * N4]);
        cp_commit();

        float4 s;
        s.x = lif_step(x.x, mem.x, cache.x);
        s.y = lif_step(x.y, mem.y, cache.y);
        s.z = lif_step(x.z, mem.z, cache.z);
        s.w = lif_step(x.w, mem.w, cache.w);

        __stcs(&out[base + t * N4], s);
    }
}

extern "C" void kernel_launch(void* const* d_in, const int* in_sizes, int n_in,
                              void* d_out, int out_size) {
    const float4* X = (const float4*)d_in[0];
    float4* out = (float4*)d_out;
    int lanes = B * N4;                 // 262,144
    lif_kernel<<<lanes / THREADS, THREADS>>>(X, out);
}